// round 11
// baseline (speedup 1.0000x reference)
#include <cuda_runtime.h>

typedef unsigned long long ull;

#define BATCH 2
#define CHAN  128
#define NTOK  784
#define SPLITS 7
#define QSPAN (NTOK / SPLITS)        /* 112 */
#define QCHUNK 28                    /* 112 = 4 * 28 */
#define INV_T (1.0f / 11.313708498984761f)
#define INV_C (1.0f / 128.0f)
#define LOG2E 1.4426950408889634f

// split-q partial sums for the output GEMM: [SPLITS][B][C][N]
__device__ float g_partial[SPLITS * BATCH * CHAN * NTOK];

// ---------------------------------------------------------------------------
// Packed fp32x2 helpers
// ---------------------------------------------------------------------------
__device__ __forceinline__ ull f32x2_fma(ull a, ull b, ull c) {
    ull r; asm("fma.rn.f32x2 %0, %1, %2, %3;" : "=l"(r) : "l"(a), "l"(b), "l"(c)); return r;
}
__device__ __forceinline__ ull dup2(float x) {
    ull r; asm("mov.b64 %0, {%1, %1};" : "=l"(r) : "f"(x)); return r;
}
__device__ __forceinline__ void unpack2(ull v, float& lo, float& hi) {
    asm("mov.b64 {%0, %1}, %2;" : "=f"(lo), "=f"(hi) : "l"(v));
}

// ---------------------------------------------------------------------------
// Kernel 1: L1-distance logits (scalar FADD, abs as free src modifier).
// logits[b,k,q] = (1/C) * sum_c | q[b,c,q]/T - k[b,c,k] |
// Tile 64(q) x 32(k), 256 threads, thread-tile 4q x 2k.
// 64-channel smem phases -> only 2 sync pairs/block; float4 global loads.
// Grid 13 x 25 x 2 = 650 blocks.
// ---------------------------------------------------------------------------
__global__ void __launch_bounds__(256)
l1_logits_kernel(const float* __restrict__ q,
                 const float* __restrict__ k,
                 float* __restrict__ attn)
{
    const int b  = blockIdx.z;
    const int q0 = blockIdx.x * 64;
    const int k0 = blockIdx.y * 32;

    __shared__ __align__(16) float qs[64][64];   // 16KB
    __shared__ __align__(16) float ks[64][32];   // 8KB

    const int tid = threadIdx.x;        // 0..255
    const int tx  = tid & 15;           // q-group: 4 q
    const int ty  = tid >> 4;           // k-group: 2 k

    const float* qb = q + (size_t)b * CHAN * NTOK;
    const float* kb = k + (size_t)b * CHAN * NTOK;

    float acc[2][4] = {};

    #pragma unroll
    for (int c0 = 0; c0 < CHAN; c0 += 64) {
        // q chunk: 64c x 64q = 1024 float4, 4 per thread (float4, clamped)
        #pragma unroll
        for (int r = 0; r < 4; r++) {
            int i   = tid + r * 256;
            int cc  = i >> 4;
            int col = (i & 15) * 4;
            int qi  = q0 + col;
            if (qi + 3 >= NTOK) qi = NTOK - 4;          // aligned clamp; never stored
            float4 t = *(const float4*)&qb[(size_t)(c0 + cc) * NTOK + qi];
            t.x *= INV_T; t.y *= INV_T; t.z *= INV_T; t.w *= INV_T;
            *(float4*)&qs[cc][col] = t;
        }
        // k chunk: 64c x 32k = 512 float4, 2 per thread
        #pragma unroll
        for (int r = 0; r < 2; r++) {
            int i   = tid + r * 256;
            int cc  = i >> 3;
            int col = (i & 7) * 4;
            int ki  = k0 + col;
            if (ki + 3 >= NTOK) ki = NTOK - 4;
            *(float4*)&ks[cc][col] = *(const float4*)&kb[(size_t)(c0 + cc) * NTOK + ki];
        }
        __syncthreads();

        #pragma unroll 8
        for (int cc = 0; cc < 64; cc++) {
            float4 rq = *(const float4*)&qs[cc][tx * 4];
            float2 rk = *(const float2*)&ks[cc][ty * 2];
            acc[0][0] += fabsf(rq.x - rk.x);
            acc[0][1] += fabsf(rq.y - rk.x);
            acc[0][2] += fabsf(rq.z - rk.x);
            acc[0][3] += fabsf(rq.w - rk.x);
            acc[1][0] += fabsf(rq.x - rk.y);
            acc[1][1] += fabsf(rq.y - rk.y);
            acc[1][2] += fabsf(rq.z - rk.y);
            acc[1][3] += fabsf(rq.w - rk.y);
        }
        __syncthreads();
    }

    float* ab = attn + (size_t)b * NTOK * NTOK;
    const int qg = q0 + tx * 4;
    if (qg < NTOK) {                            // 784 % 4 == 0: all-or-none
        #pragma unroll
        for (int j = 0; j < 2; j++) {
            int kk = k0 + ty * 2 + j;
            if (kk < NTOK) {
                float4 f;
                f.x = acc[j][0] * INV_C;
                f.y = acc[j][1] * INV_C;
                f.z = acc[j][2] * INV_C;
                f.w = acc[j][3] * INV_C;
                *(float4*)&ab[(size_t)kk * NTOK + qg] = f;
            }
        }
    }
}

// ---------------------------------------------------------------------------
// Kernel 2: in-place softmax over last dim (q). One WARP per row, 8 rows/block.
// float4 vectorized: 196 float4 per row, lane covers up to 7.
// ---------------------------------------------------------------------------
__global__ void softmax_kernel(float* __restrict__ attn)
{
    const int row  = blockIdx.x * 8 + (threadIdx.x >> 5);   // 196*8 = 1568 exact
    const int lane = threadIdx.x & 31;
    float4* a4 = (float4*)(attn + (size_t)row * NTOK);      // 196 float4

    float4 v[7];
    float mx = -1e30f;
    #pragma unroll
    for (int i = 0; i < 7; i++) {
        int idx = lane + i * 32;
        if (idx < 196) {
            v[i] = a4[idx];
            mx = fmaxf(mx, fmaxf(fmaxf(v[i].x, v[i].y), fmaxf(v[i].z, v[i].w)));
        } else {
            v[i] = make_float4(-1e30f, -1e30f, -1e30f, -1e30f);
        }
    }
    #pragma unroll
    for (int o = 16; o; o >>= 1)
        mx = fmaxf(mx, __shfl_xor_sync(0xffffffffu, mx, o));

    float s = 0.0f;
    #pragma unroll
    for (int i = 0; i < 7; i++) {
        v[i].x = exp2f((v[i].x - mx) * LOG2E);
        v[i].y = exp2f((v[i].y - mx) * LOG2E);
        v[i].z = exp2f((v[i].z - mx) * LOG2E);
        v[i].w = exp2f((v[i].w - mx) * LOG2E);
        s += (v[i].x + v[i].y) + (v[i].z + v[i].w);
    }
    #pragma unroll
    for (int o = 16; o; o >>= 1)
        s += __shfl_xor_sync(0xffffffffu, s, o);

    float inv = __frcp_rn(s);
    #pragma unroll
    for (int i = 0; i < 7; i++) {
        int idx = lane + i * 32;
        if (idx < 196) {
            v[i].x *= inv; v[i].y *= inv; v[i].z *= inv; v[i].w *= inv;
            a4[idx] = v[i];
        }
    }
}

// ---------------------------------------------------------------------------
// Kernel 3a: partial[s][b,c,k] = sum_{q in split s} v[b,c,q] * attn[b,k,q]
// Packed f32x2 over k. Tile 64(k) x 32(c), 256 threads, thread 4k(2 pairs) x 2c.
// SPLITS=7: grid 13 x 4 x 14 = 728 blocks -> ~4.9 blocks/SM.
// ---------------------------------------------------------------------------
__global__ void out_gemm_partial_kernel(const float* __restrict__ v,
                                        const float* __restrict__ attn)
{
    const int bz = blockIdx.z;
    const int b  = bz / SPLITS;         // batch
    const int s  = bz - b * SPLITS;     // split
    const int k0 = blockIdx.x * 64;
    const int c0 = blockIdx.y * 32;
    const int qbase = s * QSPAN;

    __shared__ __align__(16) float at[QCHUNK][68];   // [q][k]
    __shared__ __align__(16) ull   vd[32][QCHUNK];   // [c][q], duplicated pairs

    const int tid = threadIdx.x;
    const int tx  = tid & 15;           // k-group: 4 k = 2 pairs
    const int ty  = tid >> 4;           // c-group: 2 c

    const float* vb = v    + (size_t)b * CHAN * NTOK;
    const float* ab = attn + (size_t)b * NTOK * NTOK;

    ull acc[2][2];
    acc[0][0] = acc[0][1] = acc[1][0] = acc[1][1] = 0ULL;

    for (int qc = 0; qc < QSPAN; qc += QCHUNK) {
        const int q0 = qbase + qc;      // q0+27 <= 783 always (7*112 = 784 exact)
        // attn tile 64k x 28q -> transposed. 1792 elems, 7/thread.
        #pragma unroll
        for (int r = 0; r < 7; r++) {
            int i  = tid + r * 256;
            int kk = i / QCHUNK;
            int qq = i - kk * QCHUNK;
            int kr = k0 + kk; if (kr >= NTOK) kr = NTOK - 1;    // never stored
            at[qq][kk] = ab[(size_t)kr * NTOK + q0 + qq];
        }
        // v tile 32c x 28q -> duplicated ull. 896 elems, <=4/thread.
        #pragma unroll
        for (int r = 0; r < 4; r++) {
            int i = tid + r * 256;
            if (i < 32 * QCHUNK) {
                int cc = i / QCHUNK;
                int qq = i - cc * QCHUNK;
                vd[cc][qq] = dup2(vb[(size_t)(c0 + cc) * NTOK + q0 + qq]);
            }
        }
        __syncthreads();

        #pragma unroll
        for (int qq = 0; qq < QCHUNK; qq++) {
            ulonglong2 ap = *(const ulonglong2*)&at[qq][tx * 4];
            ull v0 = vd[ty * 2 + 0][qq];
            ull v1 = vd[ty * 2 + 1][qq];
            acc[0][0] = f32x2_fma(v0, ap.x, acc[0][0]);
            acc[0][1] = f32x2_fma(v0, ap.y, acc[0][1]);
            acc[1][0] = f32x2_fma(v1, ap.x, acc[1][0]);
            acc[1][1] = f32x2_fma(v1, ap.y, acc[1][1]);
        }
        __syncthreads();
    }

    float* pb = g_partial + ((size_t)s * BATCH + b) * CHAN * NTOK;
    const int kg = k0 + tx * 4;
    if (kg < NTOK) {                    // 784 % 4 == 0
        #pragma unroll
        for (int j = 0; j < 2; j++) {
            int cc = c0 + ty * 2 + j;
            float4 f;
            unpack2(acc[j][0], f.x, f.y);
            unpack2(acc[j][1], f.z, f.w);
            *(float4*)&pb[(size_t)cc * NTOK + kg] = f;
        }
    }
}

// ---------------------------------------------------------------------------
// Kernel 3b: out[i] = sum_s partial[s][i]  (fixed order -> deterministic)
// float2 granularity: 100352 threads -> 392 blocks; 7 loads in flight (MLP=7).
// ---------------------------------------------------------------------------
__global__ void reduce_kernel(float* __restrict__ out)
{
    const int i2 = blockIdx.x * 256 + threadIdx.x;      // float2 index
    const float2* p = (const float2*)g_partial;
    const int S = (BATCH * CHAN * NTOK) / 2;            // 100352

    float2 r[SPLITS];
    #pragma unroll
    for (int s = 0; s < SPLITS; s++)
        r[s] = p[i2 + s * S];                            // all loads issued first

    float2 a = r[0];
    #pragma unroll
    for (int s = 1; s < SPLITS; s++) { a.x += r[s].x; a.y += r[s].y; }

    ((float2*)out)[i2] = a;
}

// ---------------------------------------------------------------------------
extern "C" void kernel_launch(void* const* d_in, const int* in_sizes, int n_in,
                              void* d_out, int out_size)
{
    const float* q = (const float*)d_in[0];
    const float* k = (const float*)d_in[1];
    const float* v = (const float*)d_in[2];

    float* out_ptr  = (float*)d_out;                         // [B, C, N]
    float* attn_ptr = out_ptr + (size_t)BATCH * CHAN * NTOK; // [B, N, N]

    dim3 g1((NTOK + 63) / 64, (NTOK + 31) / 32, BATCH);      // 13 x 25 x 2 = 650
    l1_logits_kernel<<<g1, 256>>>(q, k, attn_ptr);

    softmax_kernel<<<(BATCH * NTOK) / 8, 256>>>(attn_ptr);   // 196 blocks

    dim3 g3((NTOK + 63) / 64, CHAN / 32, BATCH * SPLITS);    // 13 x 4 x 14 = 728
    out_gemm_partial_kernel<<<g3, 256>>>(v, attn_ptr);

    reduce_kernel<<<(BATCH * CHAN * NTOK) / (256 * 2), 256>>>(out_ptr);  // 392 blocks
}

// round 17
// speedup vs baseline: 1.4964x; 1.4964x over previous
#include <cuda_runtime.h>

typedef unsigned long long ull;

#define BATCH 2
#define CHAN  128
#define NTOK  784
#define SPLITS 4
#define QSPAN (NTOK / SPLITS)        /* 196 */
#define QCHUNK 28                    /* 196 = 7 * 28 */
#define INV_T (1.0f / 11.313708498984761f)
#define INV_C (1.0f / 128.0f)
#define LOG2E 1.4426950408889634f

#define KTILES 13                    /* ceil(784/64) */
#define CTILES 4                     /* 128/32 */
#define NGROUPS (BATCH * KTILES * CTILES)

// split-q partial sums for the output GEMM: [SPLITS][B][C][N]
__device__ float g_partial[SPLITS * BATCH * CHAN * NTOK];
// per-(b,ktile,ctile) arrival counters (zero-init; last block resets to 0)
__device__ unsigned int g_cnt[NGROUPS];

// ---------------------------------------------------------------------------
// Packed fp32x2 helpers
// ---------------------------------------------------------------------------
__device__ __forceinline__ ull f32x2_fma(ull a, ull b, ull c) {
    ull r; asm("fma.rn.f32x2 %0, %1, %2, %3;" : "=l"(r) : "l"(a), "l"(b), "l"(c)); return r;
}
__device__ __forceinline__ ull dup2(float x) {
    ull r; asm("mov.b64 %0, {%1, %1};" : "=l"(r) : "f"(x)); return r;
}
__device__ __forceinline__ void unpack2(ull v, float& lo, float& hi) {
    asm("mov.b64 {%0, %1}, %2;" : "=f"(lo), "=f"(hi) : "l"(v));
}

// ---------------------------------------------------------------------------
// Kernel 1: L1-distance logits (scalar FADD, abs as free src modifier).
// logits[b,k,q] = (1/C) * sum_c | q[b,c,q]/T - k[b,c,k] |
// Tile 64(q) x 32(k), 256 threads, thread-tile 4q x 2k.
// Grid 13 x 25 x 2 = 650 blocks.   (R10 configuration, verbatim)
// ---------------------------------------------------------------------------
__global__ void l1_logits_kernel(const float* __restrict__ q,
                                 const float* __restrict__ k,
                                 float* __restrict__ attn)
{
    const int b  = blockIdx.z;
    const int q0 = blockIdx.x * 64;
    const int k0 = blockIdx.y * 32;

    __shared__ __align__(16) float qs[16][64];
    __shared__ __align__(16) float ks[16][32];

    const int tid = threadIdx.x;        // 0..255
    const int tx  = tid & 15;           // q-group: 4 q
    const int ty  = tid >> 4;           // k-group: 2 k

    const float* qb = q + (size_t)b * CHAN * NTOK;
    const float* kb = k + (size_t)b * CHAN * NTOK;

    float acc[2][4] = {};

    for (int c0 = 0; c0 < CHAN; c0 += 16) {
        // q chunk: 16x64 = 1024 floats, 4/thread
        #pragma unroll
        for (int r = 0; r < 4; r++) {
            int i   = tid + r * 256;
            int cc  = i >> 6;
            int col = i & 63;
            int qi = q0 + col; if (qi >= NTOK) qi = NTOK - 1;   // clamped lanes never stored
            qs[cc][col] = qb[(size_t)(c0 + cc) * NTOK + qi] * INV_T;
        }
        // k chunk: 16x32 = 512 floats, 2/thread
        #pragma unroll
        for (int r = 0; r < 2; r++) {
            int i   = tid + r * 256;
            int cc  = i >> 5;
            int col = i & 31;
            int ki = k0 + col; if (ki >= NTOK) ki = NTOK - 1;
            ks[cc][col] = kb[(size_t)(c0 + cc) * NTOK + ki];
        }
        __syncthreads();

        #pragma unroll
        for (int cc = 0; cc < 16; cc++) {
            float rq[4], rk[2];
            #pragma unroll
            for (int i = 0; i < 4; i++) rq[i] = qs[cc][tx * 4 + i];
            #pragma unroll
            for (int j = 0; j < 2; j++) rk[j] = ks[cc][ty * 2 + j];
            #pragma unroll
            for (int j = 0; j < 2; j++)
                #pragma unroll
                for (int i = 0; i < 4; i++)
                    acc[j][i] += fabsf(rq[i] - rk[j]);
        }
        __syncthreads();
    }

    float* ab = attn + (size_t)b * NTOK * NTOK;
    const int qg = q0 + tx * 4;
    if (qg < NTOK) {                            // 784 % 4 == 0: all-or-none
        #pragma unroll
        for (int j = 0; j < 2; j++) {
            int kk = k0 + ty * 2 + j;
            if (kk < NTOK) {
                float4 f;
                f.x = acc[j][0] * INV_C;
                f.y = acc[j][1] * INV_C;
                f.z = acc[j][2] * INV_C;
                f.w = acc[j][3] * INV_C;
                *(float4*)&ab[(size_t)kk * NTOK + qg] = f;
            }
        }
    }
}

// ---------------------------------------------------------------------------
// Kernel 2: in-place softmax over last dim (q). One WARP per row, 8 rows/block.
// (R10 configuration, verbatim)
// ---------------------------------------------------------------------------
__global__ void softmax_kernel(float* __restrict__ attn)
{
    const int row  = blockIdx.x * 8 + (threadIdx.x >> 5);   // 196*8 = 1568 exact
    const int lane = threadIdx.x & 31;
    float* a = attn + (size_t)row * NTOK;

    float v[25];
    float mx = -1e30f;
    #pragma unroll
    for (int i = 0; i < 25; i++) {
        int idx = lane + i * 32;
        v[i] = (idx < NTOK) ? a[idx] : -1e30f;
        mx = fmaxf(mx, v[i]);
    }
    #pragma unroll
    for (int o = 16; o; o >>= 1)
        mx = fmaxf(mx, __shfl_xor_sync(0xffffffffu, mx, o));

    float s = 0.0f;
    #pragma unroll
    for (int i = 0; i < 25; i++) {
        v[i] = exp2f((v[i] - mx) * LOG2E);   // OOB lanes -> 0
        s += v[i];
    }
    #pragma unroll
    for (int o = 16; o; o >>= 1)
        s += __shfl_xor_sync(0xffffffffu, s, o);

    float inv = __frcp_rn(s);
    #pragma unroll
    for (int i = 0; i < 25; i++) {
        int idx = lane + i * 32;
        if (idx < NTOK) a[idx] = v[i] * inv;
    }
}

// ---------------------------------------------------------------------------
// Kernel 3: partial[s][b,c,k] = sum_{q in split s} v[b,c,q] * attn[b,k,q],
// then the LAST block of each (b, k-tile, c-tile) group sums the SPLITS
// partials in fixed s-order (bit-deterministic) and writes out[b,c,k].
// Packed f32x2 over k. Tile 64(k) x 32(c), 256 threads, thread 4k(2 pairs) x 2c.
// Grid 13 x 4 x (B*SPLITS=8) = 416 blocks.
// ---------------------------------------------------------------------------
__global__ void out_gemm_partial_kernel(const float* __restrict__ v,
                                        const float* __restrict__ attn,
                                        float* __restrict__ out)
{
    const int bz = blockIdx.z;
    const int b  = bz >> 2;             // batch
    const int s  = bz & 3;              // split
    const int k0 = blockIdx.x * 64;
    const int c0 = blockIdx.y * 32;
    const int qbase = s * QSPAN;

    __shared__ __align__(16) float at[QCHUNK][68];   // [q][k]
    __shared__ __align__(16) ull   vd[32][QCHUNK];   // [c][q], duplicated pairs
    __shared__ unsigned int s_last;

    const int tid = threadIdx.x;
    const int tx  = tid & 15;           // k-group: 4 k = 2 pairs
    const int ty  = tid >> 4;           // c-group: 2 c

    const float* vb = v    + (size_t)b * CHAN * NTOK;
    const float* ab = attn + (size_t)b * NTOK * NTOK;

    ull acc[2][2];
    acc[0][0] = acc[0][1] = acc[1][0] = acc[1][1] = 0ULL;

    for (int qc = 0; qc < QSPAN; qc += QCHUNK) {
        const int q0 = qbase + qc;
        // attn tile 64k x 28q -> transposed. 1792 elems, 7/thread.
        #pragma unroll
        for (int r = 0; r < 7; r++) {
            int i  = tid + r * 256;
            int kk = i / QCHUNK;
            int qq = i - kk * QCHUNK;
            int kr = k0 + kk; if (kr >= NTOK) kr = NTOK - 1;    // never stored
            at[qq][kk] = ab[(size_t)kr * NTOK + q0 + qq];
        }
        // v tile 32c x 28q -> duplicated ull. 896 elems, <=4/thread.
        #pragma unroll
        for (int r = 0; r < 4; r++) {
            int i = tid + r * 256;
            if (i < 32 * QCHUNK) {
                int cc = i / QCHUNK;
                int qq = i - cc * QCHUNK;
                vd[cc][qq] = dup2(vb[(size_t)(c0 + cc) * NTOK + q0 + qq]);
            }
        }
        __syncthreads();

        #pragma unroll
        for (int qq = 0; qq < QCHUNK; qq++) {
            ulonglong2 ap = *(const ulonglong2*)&at[qq][tx * 4];
            ull v0 = vd[ty * 2 + 0][qq];
            ull v1 = vd[ty * 2 + 1][qq];
            acc[0][0] = f32x2_fma(v0, ap.x, acc[0][0]);
            acc[0][1] = f32x2_fma(v0, ap.y, acc[0][1]);
            acc[1][0] = f32x2_fma(v1, ap.x, acc[1][0]);
            acc[1][1] = f32x2_fma(v1, ap.y, acc[1][1]);
        }
        __syncthreads();
    }

    // write this split's partial tile
    float* pb = g_partial + ((size_t)s * BATCH + b) * CHAN * NTOK;
    const int kg = k0 + tx * 4;
    if (kg < NTOK) {                    // 784 % 4 == 0
        #pragma unroll
        for (int j = 0; j < 2; j++) {
            int cc = c0 + ty * 2 + j;
            float4 f;
            unpack2(acc[j][0], f.x, f.y);
            unpack2(acc[j][1], f.z, f.w);
            *(float4*)&pb[(size_t)cc * NTOK + kg] = f;
        }
    }

    // ---- last-block reduction (threadFenceReduction pattern) ----
    __threadfence();
    const int grp = (b * CTILES + blockIdx.y) * KTILES + blockIdx.x;
    if (tid == 0) {
        unsigned int old = atomicAdd(&g_cnt[grp], 1u);
        s_last = (old == SPLITS - 1) ? 1u : 0u;
    }
    __syncthreads();

    if (s_last) {
        // sum the 4 partials for this 64k x 32c tile, fixed s-order.
        float* ob = out + (size_t)b * CHAN * NTOK;
        const float* p0 = g_partial + (size_t)b * CHAN * NTOK;
        const size_t sstep = (size_t)BATCH * CHAN * NTOK;

        #pragma unroll
        for (int t = tid; t < 512; t += 256) {       // 32c x 16 float4
            int cc = t >> 4;
            int f4 = t & 15;
            int kk = k0 + f4 * 4;
            if (kk < NTOK) {
                size_t off = (size_t)(c0 + cc) * NTOK + kk;
                float4 r0 = *(const float4*)&p0[off];
                float4 r1 = *(const float4*)&p0[off + sstep];
                float4 r2 = *(const float4*)&p0[off + 2 * sstep];
                float4 r3 = *(const float4*)&p0[off + 3 * sstep];
                float4 a;
                a.x = ((r0.x + r1.x) + (r2.x + r3.x));
                a.y = ((r0.y + r1.y) + (r2.y + r3.y));
                a.z = ((r0.z + r1.z) + (r2.z + r3.z));
                a.w = ((r0.w + r1.w) + (r2.w + r3.w));
                *(float4*)&ob[off] = a;
            }
        }
        if (tid == 0) g_cnt[grp] = 0;    // reset for the next invocation/replay
    }
}

// ---------------------------------------------------------------------------
extern "C" void kernel_launch(void* const* d_in, const int* in_sizes, int n_in,
                              void* d_out, int out_size)
{
    const float* q = (const float*)d_in[0];
    const float* k = (const float*)d_in[1];
    const float* v = (const float*)d_in[2];

    float* out_ptr  = (float*)d_out;                         // [B, C, N]
    float* attn_ptr = out_ptr + (size_t)BATCH * CHAN * NTOK; // [B, N, N]

    dim3 g1((NTOK + 63) / 64, (NTOK + 31) / 32, BATCH);      // 13 x 25 x 2 = 650
    l1_logits_kernel<<<g1, 256>>>(q, k, attn_ptr);

    softmax_kernel<<<(BATCH * NTOK) / 8, 256>>>(attn_ptr);   // 196 blocks

    dim3 g3((NTOK + 63) / 64, CHAN / 32, BATCH * SPLITS);    // 13 x 4 x 8 = 416
    out_gemm_partial_kernel<<<g3, 256>>>(v, attn_ptr, out_ptr);
}